// round 7
// baseline (speedup 1.0000x reference)
#include <cuda_runtime.h>
#include <math.h>

#define NMAX 100000
#define EMAX 600000
#define NBMAX 512

// ---------------- scratch (device globals: no allocation allowed) ----------
__device__ float4 g_h0[NMAX];           // normalized input features (x,y,area,0)
__device__ float4 g_agg0[NMAX];         // conv1 aggregate; .w = degree
__device__ float4 g_h1[NMAX * 32];      // conv1 output      [node][128]
__device__ float4 g_agg1[NMAX * 32];    // conv2 aggregate/deg [node][128]
__device__ float4 g_h2[NMAX * 32];      // conv2 output      [node][128]
__device__ int    g_cnt[NMAX];          // per-dst edge counts / fill cursors
__device__ int    g_tmp[NMAX];          // block-local exclusive prefix
__device__ int    g_bsum[NBMAX];        // per-block totals
__device__ int    g_boff[NBMAX];        // per-block offsets
__device__ int    g_rowptr[NMAX + 1];   // CSR row pointers (by destination)
__device__ int    g_elist[EMAX];        // CSR column list: source node ids
__device__ float    g_stats[8];         // sums for _normalize
__device__ unsigned g_statu[8];         // encoded min/max
__device__ int    g_ei64;               // 1 if edge_index is int64, 0 if int32

__device__ __forceinline__ float finf() { return __int_as_float(0x7f800000); }

// order-preserving float<->uint encode (atomicMin/Max on unsigned == float order)
__device__ __forceinline__ unsigned fenc(float f) {
    unsigned u = __float_as_uint(f);
    return u ^ ((unsigned)((int)u >> 31) | 0x80000000u);
}
__device__ __forceinline__ float fdec(unsigned e) {
    unsigned u = (e & 0x80000000u) ? (e ^ 0x80000000u) : ~e;
    return __uint_as_float(u);
}

// packed f32x2 helpers (Blackwell FFMA2 path — only reachable via PTX)
__device__ __forceinline__ unsigned long long pk2(float lo, float hi) {
    unsigned long long r;
    asm("mov.b64 %0, {%1, %2};" : "=l"(r) : "f"(lo), "f"(hi));
    return r;
}
__device__ __forceinline__ unsigned long long fma2(unsigned long long a,
        unsigned long long b, unsigned long long c) {
    unsigned long long d;
    asm("fma.rn.f32x2 %0, %1, %2, %3;" : "=l"(d) : "l"(a), "l"(b), "l"(c));
    return d;
}
__device__ __forceinline__ void upk2(float& lo, float& hi, unsigned long long v) {
    asm("mov.b64 {%0, %1}, %2;" : "=f"(lo), "=f"(hi) : "l"(v));
}

// Fetch edge endpoint #i from a buffer of unknown (int32 vs int64) dtype.
__device__ __forceinline__ int edge_at(const int* ei32, int i) {
    return g_ei64 ? (int)((const long long*)ei32)[i] : ei32[i];
}

// ---------------- init + dtype probe ---------------------------------------
__global__ void k_init(const int* __restrict__ ei32, int n) {
    int i = blockIdx.x * blockDim.x + threadIdx.x;
    if (i < n) g_cnt[i] = 0;
    if (i == 0) {
        g_statu[0] = 0xFFFFFFFFu; g_statu[1] = 0u;   // min/max x0
        g_statu[2] = 0xFFFFFFFFu; g_statu[3] = 0u;   // min/max x1
        g_statu[4] = 0u;                              // max area
        g_statu[5] = 0u; g_statu[6] = 0u;             // max r0, r1
        g_stats[0] = 0.f; g_stats[1] = 0.f;           // sum r0, sum r1
        int acc = 0;
        #pragma unroll
        for (int j = 0; j < 128; j++) acc |= ei32[2 * j + 1];
        g_ei64 = (acc == 0) ? 1 : 0;                  // int64 => high words zero
    }
}

// ---------------- CSR build: count / scan / fill ---------------------------
__global__ void k_count(const int* __restrict__ ei, int nE, int n) {
    int i = blockIdx.x * blockDim.x + threadIdx.x;
    if (i >= nE) return;
    int d = edge_at(ei, nE + i);
    d = min(max(d, 0), n - 1);
    atomicAdd(&g_cnt[d], 1);
}

__global__ void k_scan1(int n) {
    __shared__ int sm[256];
    int t = threadIdx.x;
    int i = blockIdx.x * 256 + t;
    int v = (i < n) ? g_cnt[i] : 0;
    sm[t] = v; __syncthreads();
    for (int o = 1; o < 256; o <<= 1) {
        int u = (t >= o) ? sm[t - o] : 0;
        __syncthreads();
        sm[t] += u;
        __syncthreads();
    }
    if (i < n) g_tmp[i] = sm[t] - v;          // block-local exclusive
    if (t == 255) g_bsum[blockIdx.x] = sm[255];
}

__global__ void k_scan2(int nb, int n) {
    __shared__ int sm[NBMAX];
    int t = threadIdx.x;
    int v = (t < nb) ? g_bsum[t] : 0;
    sm[t] = v; __syncthreads();
    for (int o = 1; o < NBMAX; o <<= 1) {
        int u = (t >= o) ? sm[t - o] : 0;
        __syncthreads();
        sm[t] += u;
        __syncthreads();
    }
    if (t < nb) g_boff[t] = sm[t] - v;        // exclusive block offsets
    if (t == nb - 1) g_rowptr[n] = sm[t];     // grand total
}

__global__ void k_scan3(int n) {
    int i = blockIdx.x * blockDim.x + threadIdx.x;
    if (i >= n) return;
    g_rowptr[i] = g_tmp[i] + g_boff[blockIdx.x];
    g_cnt[i] = 0;                              // reuse as fill cursor
}

__global__ void k_fill(const int* __restrict__ ei, int nE, int n) {
    int i = blockIdx.x * blockDim.x + threadIdx.x;
    if (i >= nE) return;
    int s = edge_at(ei, i);
    int d = edge_at(ei, nE + i);
    s = min(max(s, 0), n - 1);
    d = min(max(d, 0), n - 1);
    int pos = atomicAdd(&g_cnt[d], 1);
    g_elist[g_rowptr[d] + pos] = s;
}

// ---------------- normalize pass 1: min/max of raw coords, max area --------
__global__ void k_stats1(const float* __restrict__ x, int n) {
    int i = blockIdx.x * blockDim.x + threadIdx.x;
    float mn0 = finf(), mx0 = -finf(), mn1 = finf(), mx1 = -finf(), mxA = -finf();
    if (i < n) {
        float a = x[3 * i], b = x[3 * i + 1], c = x[3 * i + 2];
        mn0 = mx0 = a; mn1 = mx1 = b; mxA = c;
    }
    #pragma unroll
    for (int o = 16; o; o >>= 1) {
        mn0 = fminf(mn0, __shfl_xor_sync(0xffffffffu, mn0, o));
        mx0 = fmaxf(mx0, __shfl_xor_sync(0xffffffffu, mx0, o));
        mn1 = fminf(mn1, __shfl_xor_sync(0xffffffffu, mn1, o));
        mx1 = fmaxf(mx1, __shfl_xor_sync(0xffffffffu, mx1, o));
        mxA = fmaxf(mxA, __shfl_xor_sync(0xffffffffu, mxA, o));
    }
    if ((threadIdx.x & 31) == 0) {
        atomicMin(&g_statu[0], fenc(mn0)); atomicMax(&g_statu[1], fenc(mx0));
        atomicMin(&g_statu[2], fenc(mn1)); atomicMax(&g_statu[3], fenc(mx1));
        atomicMax(&g_statu[4], fenc(mxA));
    }
}

// ---------------- normalize pass 2: (conditionally) rotate, sum & max ------
__global__ void k_rot(const float* __restrict__ x, int n) {
    int i = blockIdx.x * blockDim.x + threadIdx.x;
    bool rot = (fdec(g_statu[3]) - fdec(g_statu[2])) > (fdec(g_statu[1]) - fdec(g_statu[0]));
    float s0 = 0.f, s1 = 0.f, m0 = -finf(), m1 = -finf();
    if (i < n) {
        float a = x[3 * i], b = x[3 * i + 1], ar = x[3 * i + 2];
        float cc = cosf(1.5707964f);   // cos(float32(pi/2)) as jax computes it
        float ss = sinf(1.5707964f);
        float r0 = rot ? (cc * a - ss * b) : a;
        float r1 = rot ? (ss * a + cc * b) : b;
        g_h0[i] = make_float4(r0, r1, ar, 0.f);
        s0 = r0; s1 = r1; m0 = r0; m1 = r1;
    }
    #pragma unroll
    for (int o = 16; o; o >>= 1) {
        s0 += __shfl_xor_sync(0xffffffffu, s0, o);
        s1 += __shfl_xor_sync(0xffffffffu, s1, o);
        m0 = fmaxf(m0, __shfl_xor_sync(0xffffffffu, m0, o));
        m1 = fmaxf(m1, __shfl_xor_sync(0xffffffffu, m1, o));
    }
    if ((threadIdx.x & 31) == 0) {
        atomicAdd(&g_stats[0], s0); atomicAdd(&g_stats[1], s1);
        atomicMax(&g_statu[5], fenc(m0)); atomicMax(&g_statu[6], fenc(m1));
    }
}

// ---------------- normalize pass 3: center/scale ---------------------------
__global__ void k_norm(int n) {
    int i = blockIdx.x * blockDim.x + threadIdx.x;
    if (i >= n) return;
    float me0 = g_stats[0] / (float)n;
    float me1 = g_stats[1] / (float)n;
    float4 v = g_h0[i];
    v.x = (v.x - me0) / fdec(g_statu[5]);
    v.y = (v.y - me1) / fdec(g_statu[6]);
    v.z = v.z / fdec(g_statu[4]);
    v.w = 0.f;
    g_h0[i] = v;
}

// ---------------- conv1 aggregate: CSR gather, thread per node -------------
__global__ void k_aggc1(int n) {
    int i = blockIdx.x * blockDim.x + threadIdx.x;
    if (i >= n) return;
    int beg = g_rowptr[i], end = g_rowptr[i + 1];
    float sx = 0.f, sy = 0.f, sz = 0.f;
    for (int j = beg; j < end; j++) {
        int s = g_elist[j];
        float4 v = g_h0[s];
        sx += v.x; sy += v.y; sz += v.z;
    }
    g_agg0[i] = make_float4(sx, sy, sz, (float)(end - beg));
}

// ---------------- conv1 compute: h1 = tanh(Wl1*agg/deg + bl1 + Wr1*h0) -----
__global__ void k_conv1(const float* __restrict__ Wl, const float* __restrict__ bl,
                        const float* __restrict__ Wr, int n) {
    __shared__ float wl[384], wr[384], bb[128];
    int tid = threadIdx.x;
    if (tid < 128) bb[tid] = bl[tid];
    for (int j = tid; j < 384; j += blockDim.x) { wl[j] = Wl[j]; wr[j] = Wr[j]; }
    __syncthreads();
    int i = blockIdx.x * 2 + (tid >> 7);
    if (i >= n) return;
    int c = tid & 127;
    float4 ag = g_agg0[i];
    float inv = 1.0f / fmaxf(ag.w, 1.0f);
    float4 h = g_h0[i];
    float v = bb[c]
        + wl[c * 3 + 0] * (ag.x * inv) + wl[c * 3 + 1] * (ag.y * inv) + wl[c * 3 + 2] * (ag.z * inv)
        + wr[c * 3 + 0] * h.x + wr[c * 3 + 1] * h.y + wr[c * 3 + 2] * h.z;
    ((float*)g_h1)[i * 128 + c] = tanhf(v);
}

// ---------------- conv2 aggregate: warp per node, full occupancy -----------
// No smem => many blocks/SM; the 76.8MB of L2 neighbor reads run at
// concurrency-limited (not latency-limited) throughput.
__global__ void k_aggc2(int n) {
    int node = blockIdx.x * 8 + (threadIdx.x >> 5);
    if (node >= n) return;
    int lane = threadIdx.x & 31;
    int beg = g_rowptr[node], end = g_rowptr[node + 1];
    int cnt = end - beg;
    float4 acc = make_float4(0.f, 0.f, 0.f, 0.f);
    for (int base = beg; base < end; base += 32) {
        int m = min(end - base, 32);
        int sv = (lane < m) ? g_elist[base + lane] : 0;
        for (int j = 0; j < m; j++) {
            int s = __shfl_sync(0xffffffffu, sv, j);
            float4 v = g_h1[s * 32 + lane];
            acc.x += v.x; acc.y += v.y; acc.z += v.z; acc.w += v.w;
        }
    }
    float inv = 1.0f / fmaxf((float)cnt, 1.0f);
    acc.x *= inv; acc.y *= inv; acc.z *= inv; acc.w *= inv;
    g_agg1[node * 32 + lane] = acc;
}

// ---------------- conv2 GEMM: h2 = tanh([agg | h1] @ [Wl2|Wr2]^T + bl2) ----
__global__ __launch_bounds__(256) void k_conv2(const float* __restrict__ Wl,
        const float* __restrict__ bl, const float* __restrict__ Wr, int n) {
    extern __shared__ float sm[];
    float* Wc = sm;                    // [256][128] k-major (LDS.128 conflict-free)
    float* As = sm + 256 * 128;        // [64][256]
    float* bs = As + 64 * 256;         // [128]
    int tid = threadIdx.x;
    for (int idx = tid; idx < 128 * 256; idx += 256) {
        int c = idx >> 8;
        int k = idx & 255;
        float w = (k < 128) ? Wl[c * 128 + k] : Wr[c * 128 + (k - 128)];
        Wc[k * 128 + c] = w;
    }
    if (tid < 128) bs[tid] = bl[tid];
    int base = blockIdx.x * 64;
    for (int f = tid; f < 64 * 64; f += 256) {
        int nl = f >> 6;
        int kq = f & 63;
        int node = base + nl;
        float4 v = make_float4(0.f, 0.f, 0.f, 0.f);
        if (node < n)
            v = (kq < 32) ? g_agg1[node * 32 + kq] : g_h1[node * 32 + (kq - 32)];
        ((float4*)As)[nl * 64 + kq] = v;
    }
    __syncthreads();
    int warp = tid >> 5, lane = tid & 31;
    const float* ap = As + warp * 8 * 256;
    int c0 = lane * 4;
    unsigned long long acc01[8], acc23[8];
    #pragma unroll
    for (int a = 0; a < 8; a++) { acc01[a] = 0ull; acc23[a] = 0ull; }
    #pragma unroll 4
    for (int k = 0; k < 256; k++) {
        float4 w = *(const float4*)(Wc + k * 128 + c0);
        unsigned long long w01 = pk2(w.x, w.y);
        unsigned long long w23 = pk2(w.z, w.w);
        #pragma unroll
        for (int nn = 0; nn < 8; nn++) {
            float a = ap[nn * 256 + k];
            unsigned long long a2 = pk2(a, a);
            acc01[nn] = fma2(a2, w01, acc01[nn]);
            acc23[nn] = fma2(a2, w23, acc23[nn]);
        }
    }
    #pragma unroll
    for (int nn = 0; nn < 8; nn++) {
        int node = base + warp * 8 + nn;
        if (node < n) {
            float a0, a1, a2, a3;
            upk2(a0, a1, acc01[nn]);
            upk2(a2, a3, acc23[nn]);
            float4 o;
            o.x = tanhf(a0 + bs[c0 + 0]);
            o.y = tanhf(a1 + bs[c0 + 1]);
            o.z = tanhf(a2 + bs[c0 + 2]);
            o.w = tanhf(a3 + bs[c0 + 3]);
            g_h2[node * 32 + lane] = o;
        }
    }
}

// ---------------- head: t = tanh(h2@W1^T+b1); out = softmax(t@W2^T+b2) -----
// Lane owns t-channels {lane*4..+3} and {128+lane*4..+3} — both LDS.128
// conflict-free. Epilogue hoists W2 rows (64 LDS/thread vs 512 before).
__global__ __launch_bounds__(256) void k_head(const float* __restrict__ W1,
        const float* __restrict__ b1, const float* __restrict__ W2,
        const float* __restrict__ b2, float* __restrict__ out, int n) {
    extern __shared__ float sm[];
    float* W1s = sm;                   // [128][256] k-major
    float* As  = W1s + 128 * 256;      // [64][128]
    float* W2s = As + 64 * 128;        // [8][256]
    float* b1s = W2s + 2048;           // [256]
    float* b2s = b1s + 256;            // [8]
    int tid = threadIdx.x;
    for (int idx = tid; idx < 256 * 128; idx += 256) {
        int c = idx >> 7;
        int k = idx & 127;
        W1s[k * 256 + c] = W1[c * 128 + k];
    }
    for (int idx = tid; idx < 2048; idx += 256) W2s[idx] = W2[idx];
    b1s[tid] = b1[tid];
    if (tid < 8) b2s[tid] = b2[tid];
    int base = blockIdx.x * 64;
    for (int f = tid; f < 64 * 32; f += 256) {
        int nl = f >> 5, kq = f & 31;
        int node = base + nl;
        float4 v = make_float4(0.f, 0.f, 0.f, 0.f);
        if (node < n) v = g_h2[node * 32 + kq];
        ((float4*)As)[nl * 32 + kq] = v;
    }
    __syncthreads();
    int warp = tid >> 5, lane = tid & 31;
    const float* ap = As + warp * 8 * 128;
    int cA = lane * 4;          // channels cA..cA+3
    int cB = 128 + lane * 4;    // channels cB..cB+3
    unsigned long long acc[8][4];
    #pragma unroll
    for (int a = 0; a < 8; a++)
        #pragma unroll
        for (int b = 0; b < 4; b++) acc[a][b] = 0ull;
    #pragma unroll 2
    for (int k = 0; k < 128; k++) {
        float4 w0 = *(const float4*)(W1s + k * 256 + cA);
        float4 w1 = *(const float4*)(W1s + k * 256 + cB);
        unsigned long long wp0 = pk2(w0.x, w0.y);
        unsigned long long wp1 = pk2(w0.z, w0.w);
        unsigned long long wp2 = pk2(w1.x, w1.y);
        unsigned long long wp3 = pk2(w1.z, w1.w);
        #pragma unroll
        for (int nn = 0; nn < 8; nn++) {
            float a = ap[nn * 128 + k];
            unsigned long long a2 = pk2(a, a);
            acc[nn][0] = fma2(a2, wp0, acc[nn][0]);
            acc[nn][1] = fma2(a2, wp1, acc[nn][1]);
            acc[nn][2] = fma2(a2, wp2, acc[nn][2]);
            acc[nn][3] = fma2(a2, wp3, acc[nn][3]);
        }
    }
    // tanh all 64 t-values first
    float tt[8][8];
    #pragma unroll
    for (int nn = 0; nn < 8; nn++) {
        float v0, v1;
        upk2(v0, v1, acc[nn][0]); tt[nn][0] = tanhf(v0 + b1s[cA + 0]); tt[nn][1] = tanhf(v1 + b1s[cA + 1]);
        upk2(v0, v1, acc[nn][1]); tt[nn][2] = tanhf(v0 + b1s[cA + 2]); tt[nn][3] = tanhf(v1 + b1s[cA + 3]);
        upk2(v0, v1, acc[nn][2]); tt[nn][4] = tanhf(v0 + b1s[cB + 0]); tt[nn][5] = tanhf(v1 + b1s[cB + 1]);
        upk2(v0, v1, acc[nn][3]); tt[nn][6] = tanhf(v0 + b1s[cB + 2]); tt[nn][7] = tanhf(v1 + b1s[cB + 3]);
    }
    // partial logits: j-outer, W2 row hoisted
    float p[8][8];
    #pragma unroll
    for (int a = 0; a < 8; a++)
        #pragma unroll
        for (int b = 0; b < 8; b++) p[a][b] = 0.f;
    #pragma unroll
    for (int j = 0; j < 8; j++) {
        int ch = (j < 4) ? (cA + j) : (cB + j - 4);
        float w2v[8];
        #pragma unroll
        for (int c = 0; c < 8; c++) w2v[c] = W2s[c * 256 + ch];
        #pragma unroll
        for (int nn = 0; nn < 8; nn++) {
            float t = tt[nn][j];
            #pragma unroll
            for (int c = 0; c < 8; c++)
                p[nn][c] = fmaf(t, w2v[c], p[nn][c]);
        }
    }
    // butterfly reduce partial logits across the warp
    #pragma unroll
    for (int o = 16; o; o >>= 1) {
        #pragma unroll
        for (int nn = 0; nn < 8; nn++)
            #pragma unroll
            for (int c = 0; c < 8; c++)
                p[nn][c] += __shfl_xor_sync(0xffffffffu, p[nn][c], o);
    }
    #pragma unroll
    for (int nn = 0; nn < 8; nn++) {
        if (lane == nn) {
            int node = base + warp * 8 + nn;
            if (node < n) {
                float l[8], m = -finf();
                #pragma unroll
                for (int c = 0; c < 8; c++) { l[c] = p[nn][c] + b2s[c]; m = fmaxf(m, l[c]); }
                float s = 0.f;
                #pragma unroll
                for (int c = 0; c < 8; c++) { l[c] = expf(l[c] - m); s += l[c]; }
                float inv = 1.0f / s;
                float4 o0 = make_float4(l[0] * inv, l[1] * inv, l[2] * inv, l[3] * inv);
                float4 o1 = make_float4(l[4] * inv, l[5] * inv, l[6] * inv, l[7] * inv);
                *(float4*)(out + node * 8) = o0;
                *(float4*)(out + node * 8 + 4) = o1;
            }
        }
    }
}

// ---------------- launch ---------------------------------------------------
extern "C" void kernel_launch(void* const* d_in, const int* in_sizes, int n_in,
                              void* d_out, int out_size) {
    const float* x = 0; const int* ei = 0;
    const float *Wl1 = 0, *bl1 = 0, *Wr1 = 0, *Wl2 = 0, *bl2 = 0, *Wr2 = 0;
    const float *W1 = 0, *b1 = 0, *W2 = 0, *b2 = 0;
    int n = 100000, nE = 600000;
    for (int i = 0; i < n_in; i++) {
        int sz = in_sizes[i];
        const void* p = d_in[i];
        switch (sz) {
            case 300000:  x  = (const float*)p; n  = sz / 3; break;
            case 1200000: ei = (const int*)p; nE = sz / 2; break;
            case 384:     if (!Wl1) Wl1 = (const float*)p; else Wr1 = (const float*)p; break;
            case 128:     if (!bl1) bl1 = (const float*)p; else bl2 = (const float*)p; break;
            case 16384:   if (!Wl2) Wl2 = (const float*)p; else Wr2 = (const float*)p; break;
            case 32768:   W1 = (const float*)p; break;
            case 256:     b1 = (const float*)p; break;
            case 2048:    W2 = (const float*)p; break;
            case 8:       b2 = (const float*)p; break;
            default: break;
        }
    }
    float* out = (float*)d_out;
    if (n > NMAX) n = NMAX;
    if (nE > EMAX) nE = EMAX;

    const int SMEM_CONV2 = (256 * 128 + 64 * 256 + 128) * 4;                 // 196.5 KB
    const int SMEM_HEAD  = (128 * 256 + 64 * 128 + 2048 + 256 + 8) * 4;      // 173.1 KB
    cudaFuncSetAttribute(k_conv2, cudaFuncAttributeMaxDynamicSharedMemorySize, SMEM_CONV2);
    cudaFuncSetAttribute(k_head,  cudaFuncAttributeMaxDynamicSharedMemorySize, SMEM_HEAD);

    int nb = (n + 255) / 256;
    int eb = (nE + 255) / 256;
    k_init<<<nb, 256>>>(ei, n);
    k_count<<<eb, 256>>>(ei, nE, n);
    k_scan1<<<nb, 256>>>(n);
    k_scan2<<<1, NBMAX>>>(nb, n);
    k_scan3<<<nb, 256>>>(n);
    k_fill<<<eb, 256>>>(ei, nE, n);
    k_stats1<<<nb, 256>>>(x, n);
    k_rot<<<nb, 256>>>(x, n);
    k_norm<<<nb, 256>>>(n);
    k_aggc1<<<nb, 256>>>(n);
    k_conv1<<<(n + 1) / 2, 256>>>(Wl1, bl1, Wr1, n);
    k_aggc2<<<(n + 7) / 8, 256>>>(n);
    k_conv2<<<(n + 63) / 64, 256, SMEM_CONV2>>>(Wl2, bl2, Wr2, n);
    k_head<<<(n + 63) / 64, 256, SMEM_HEAD>>>(W1, b1, W2, b2, out, n);
}

// round 9
// speedup vs baseline: 1.5573x; 1.5573x over previous
#include <cuda_runtime.h>
#include <math.h>

#define NMAX 100000

// ---------------- scratch (device globals: no allocation allowed) ----------
__device__ float4 g_h0[NMAX];           // normalized input features (x,y,area,0)
__device__ float4 g_agg0[NMAX];         // conv1 aggregate; .w accumulates degree
__device__ float4 g_h1[NMAX * 32];      // conv1 output      [node][128]
__device__ float4 g_agg1[NMAX * 32];    // conv2 aggregate   [node][128]
__device__ float4 g_h2[NMAX * 32];      // conv2 output      [node][128]
__device__ float    g_stats[8];         // sums for _normalize
__device__ unsigned g_statu[8];         // encoded min/max
__device__ int    g_ei64;               // 1 if edge_index is int64, 0 if int32

__device__ __forceinline__ float finf() { return __int_as_float(0x7f800000); }

// order-preserving float<->uint encode (atomicMin/Max on unsigned == float order)
__device__ __forceinline__ unsigned fenc(float f) {
    unsigned u = __float_as_uint(f);
    return u ^ ((unsigned)((int)u >> 31) | 0x80000000u);
}
__device__ __forceinline__ float fdec(unsigned e) {
    unsigned u = (e & 0x80000000u) ? (e ^ 0x80000000u) : ~e;
    return __uint_as_float(u);
}

// fp32 -> tf32 bit pattern (round-to-nearest, keeps 10 mantissa bits)
__device__ __forceinline__ unsigned tf32u(float f) {
    unsigned r;
    asm("cvt.rna.tf32.f32 %0, %1;" : "=r"(r) : "f"(f));
    return r;
}

// m16n8k8 tf32 MMA, fp32 accumulate
__device__ __forceinline__ void mma_tf32(float* c, const unsigned* a, const unsigned* b) {
    asm volatile("mma.sync.aligned.m16n8k8.row.col.f32.tf32.tf32.f32 "
        "{%0,%1,%2,%3}, {%4,%5,%6,%7}, {%8,%9}, {%0,%1,%2,%3};"
        : "+f"(c[0]), "+f"(c[1]), "+f"(c[2]), "+f"(c[3])
        : "r"(a[0]), "r"(a[1]), "r"(a[2]), "r"(a[3]), "r"(b[0]), "r"(b[1]));
}

// vector reduction: one instruction adds 4 floats to global memory
__device__ __forceinline__ void red_add_v4(float4* addr, float a, float b, float c, float d) {
    unsigned long long ga = __cvta_generic_to_global(addr);
    asm volatile("red.global.add.v4.f32 [%0], {%1, %2, %3, %4};"
                 :: "l"(ga), "f"(a), "f"(b), "f"(c), "f"(d) : "memory");
}

// Fetch edge endpoint #i from a buffer of unknown (int32 vs int64) dtype.
__device__ __forceinline__ int edge_at(const int* ei32, int i) {
    return g_ei64 ? (int)((const long long*)ei32)[i] : ei32[i];
}

// ---------------- dtype probe: int64 edge data has zero high words ---------
__global__ void k_detect(const int* __restrict__ ei32) {
    if (threadIdx.x == 0 && blockIdx.x == 0) {
        int acc = 0;
        #pragma unroll
        for (int j = 0; j < 128; j++) acc |= ei32[2 * j + 1];
        g_ei64 = (acc == 0) ? 1 : 0;
    }
}

// ---------------- init: zero aggregates + reset stats ----------------------
__global__ void k_init(int n) {
    int i = blockIdx.x * blockDim.x + threadIdx.x;
    float4 z = make_float4(0.f, 0.f, 0.f, 0.f);
    if (i < n * 32) g_agg1[i] = z;
    if (i < n) g_agg0[i] = z;
    if (i == 0) {
        g_statu[0] = 0xFFFFFFFFu; g_statu[1] = 0u;   // min/max x0
        g_statu[2] = 0xFFFFFFFFu; g_statu[3] = 0u;   // min/max x1
        g_statu[4] = 0u;                              // max area
        g_statu[5] = 0u; g_statu[6] = 0u;             // max r0, r1
        g_stats[0] = 0.f; g_stats[1] = 0.f;           // sum r0, sum r1
    }
}

// ---------------- normalize pass 1: min/max of raw coords, max area --------
__global__ void k_stats1(const float* __restrict__ x, int n) {
    int i = blockIdx.x * blockDim.x + threadIdx.x;
    float mn0 = finf(), mx0 = -finf(), mn1 = finf(), mx1 = -finf(), mxA = -finf();
    if (i < n) {
        float a = x[3 * i], b = x[3 * i + 1], c = x[3 * i + 2];
        mn0 = mx0 = a; mn1 = mx1 = b; mxA = c;
    }
    #pragma unroll
    for (int o = 16; o; o >>= 1) {
        mn0 = fminf(mn0, __shfl_xor_sync(0xffffffffu, mn0, o));
        mx0 = fmaxf(mx0, __shfl_xor_sync(0xffffffffu, mx0, o));
        mn1 = fminf(mn1, __shfl_xor_sync(0xffffffffu, mn1, o));
        mx1 = fmaxf(mx1, __shfl_xor_sync(0xffffffffu, mx1, o));
        mxA = fmaxf(mxA, __shfl_xor_sync(0xffffffffu, mxA, o));
    }
    if ((threadIdx.x & 31) == 0) {
        atomicMin(&g_statu[0], fenc(mn0)); atomicMax(&g_statu[1], fenc(mx0));
        atomicMin(&g_statu[2], fenc(mn1)); atomicMax(&g_statu[3], fenc(mx1));
        atomicMax(&g_statu[4], fenc(mxA));
    }
}

// ---------------- normalize pass 2: (conditionally) rotate, sum & max ------
__global__ void k_rot(const float* __restrict__ x, int n) {
    int i = blockIdx.x * blockDim.x + threadIdx.x;
    bool rot = (fdec(g_statu[3]) - fdec(g_statu[2])) > (fdec(g_statu[1]) - fdec(g_statu[0]));
    float s0 = 0.f, s1 = 0.f, m0 = -finf(), m1 = -finf();
    if (i < n) {
        float a = x[3 * i], b = x[3 * i + 1], ar = x[3 * i + 2];
        float cc = cosf(1.5707964f);   // cos(float32(pi/2)) as jax computes it
        float ss = sinf(1.5707964f);
        float r0 = rot ? (cc * a - ss * b) : a;
        float r1 = rot ? (ss * a + cc * b) : b;
        g_h0[i] = make_float4(r0, r1, ar, 0.f);
        s0 = r0; s1 = r1; m0 = r0; m1 = r1;
    }
    #pragma unroll
    for (int o = 16; o; o >>= 1) {
        s0 += __shfl_xor_sync(0xffffffffu, s0, o);
        s1 += __shfl_xor_sync(0xffffffffu, s1, o);
        m0 = fmaxf(m0, __shfl_xor_sync(0xffffffffu, m0, o));
        m1 = fmaxf(m1, __shfl_xor_sync(0xffffffffu, m1, o));
    }
    if ((threadIdx.x & 31) == 0) {
        atomicAdd(&g_stats[0], s0); atomicAdd(&g_stats[1], s1);
        atomicMax(&g_statu[5], fenc(m0)); atomicMax(&g_statu[6], fenc(m1));
    }
}

// ---------------- normalize pass 3: center/scale ---------------------------
__global__ void k_norm(int n) {
    int i = blockIdx.x * blockDim.x + threadIdx.x;
    if (i >= n) return;
    float me0 = g_stats[0] / (float)n;
    float me1 = g_stats[1] / (float)n;
    float4 v = g_h0[i];
    v.x = (v.x - me0) / fdec(g_statu[5]);
    v.y = (v.y - me1) / fdec(g_statu[6]);
    v.z = v.z / fdec(g_statu[4]);
    v.w = 0.f;
    g_h0[i] = v;
}

// ---------------- conv1 scatter: 3-dim messages + degree -------------------
__global__ void k_agg1(const int* __restrict__ ei, int nE, int n) {
    int i = blockIdx.x * blockDim.x + threadIdx.x;
    if (i >= nE) return;
    int s = edge_at(ei, i);
    int d = edge_at(ei, nE + i);
    s = min(max(s, 0), n - 1);
    d = min(max(d, 0), n - 1);
    float4 v = g_h0[s];
    red_add_v4(&g_agg0[d], v.x, v.y, v.z, 1.0f);
}

// ---------------- conv1 compute: h1 = tanh(Wl1*agg/deg + bl1 + Wr1*h0) -----
__global__ void k_conv1(const float* __restrict__ Wl, const float* __restrict__ bl,
                        const float* __restrict__ Wr, int n) {
    __shared__ float wl[384], wr[384], bb[128];
    int tid = threadIdx.x;
    if (tid < 128) bb[tid] = bl[tid];
    for (int j = tid; j < 384; j += blockDim.x) { wl[j] = Wl[j]; wr[j] = Wr[j]; }
    __syncthreads();
    int i = blockIdx.x * 2 + (tid >> 7);
    if (i >= n) return;
    int c = tid & 127;
    float4 ag = g_agg0[i];
    float inv = 1.0f / fmaxf(ag.w, 1.0f);
    float4 h = g_h0[i];
    float v = bb[c]
        + wl[c * 3 + 0] * (ag.x * inv) + wl[c * 3 + 1] * (ag.y * inv) + wl[c * 3 + 2] * (ag.z * inv)
        + wr[c * 3 + 0] * h.x + wr[c * 3 + 1] * h.y + wr[c * 3 + 2] * h.z;
    ((float*)g_h1)[i * 128 + c] = tanhf(v);
}

// ---------------- conv2 scatter: warp per edge, one RED.128 per lane -------
__global__ void k_agg2(const int* __restrict__ ei, int nE, int n) {
    int e = blockIdx.x * 8 + (threadIdx.x >> 5);
    if (e >= nE) return;
    int lane = threadIdx.x & 31;
    int s = edge_at(ei, e);
    int d = edge_at(ei, nE + e);
    s = min(max(s, 0), n - 1);
    d = min(max(d, 0), n - 1);
    float4 v = g_h1[s * 32 + lane];
    red_add_v4(&g_agg1[d * 32 + lane], v.x, v.y, v.z, v.w);
}

// ---------------- conv2: tf32 MMA GEMM, h2 = tanh([agg/deg|h1]@W^T + b) ----
// Tile 64 nodes x 128 ch, K=256. Warp = m16 x n64. Smem strides padded for
// conflict-free fragment loads: As stride 260 ((4m+k)%32 distinct),
// Wc stride 136 ((8k+n)%32 distinct).
__global__ __launch_bounds__(256) void k_conv2(const float* __restrict__ Wl,
        const float* __restrict__ bl, const float* __restrict__ Wr, int n) {
    extern __shared__ float sm[];
    float* Wc = sm;                    // [256][136] tf32, k-major
    float* As = sm + 256 * 136;        // [64][260] tf32
    float* bs = As + 64 * 260;         // [128]
    unsigned* Wcu = (unsigned*)Wc;
    unsigned* Asu = (unsigned*)As;
    int tid = threadIdx.x;
    for (int idx = tid; idx < 128 * 256; idx += 256) {
        int c = idx >> 8;
        int k = idx & 255;
        float w = (k < 128) ? Wl[c * 128 + k] : Wr[c * 128 + (k - 128)];
        Wcu[k * 136 + c] = tf32u(w);
    }
    if (tid < 128) bs[tid] = bl[tid];
    int base = blockIdx.x * 64;
    for (int f = tid; f < 64 * 64; f += 256) {
        int nl = f >> 6;
        int kq = f & 63;
        int node = base + nl;
        float4 v = make_float4(0.f, 0.f, 0.f, 0.f);
        if (node < n) {
            if (kq < 32) {
                v = g_agg1[node * 32 + kq];
                float inv = 1.0f / fmaxf(g_agg0[node].w, 1.0f);
                v.x *= inv; v.y *= inv; v.z *= inv; v.w *= inv;
            } else {
                v = g_h1[node * 32 + (kq - 32)];
            }
        }
        uint4 u = make_uint4(tf32u(v.x), tf32u(v.y), tf32u(v.z), tf32u(v.w));
        *(uint4*)(Asu + nl * 260 + kq * 4) = u;
    }
    __syncthreads();
    int warp = tid >> 5, lane = tid & 31;
    int r = lane >> 2, tig = lane & 3;
    int mbase = (warp & 3) * 16;
    int nbase = (warp >> 2) * 64;
    float acc[8][4];
    #pragma unroll
    for (int a = 0; a < 8; a++) { acc[a][0] = acc[a][1] = acc[a][2] = acc[a][3] = 0.f; }
    for (int kb = 0; kb < 256; kb += 8) {
        unsigned a[4];
        a[0] = Asu[(mbase + r) * 260 + kb + tig];
        a[1] = Asu[(mbase + r + 8) * 260 + kb + tig];
        a[2] = Asu[(mbase + r) * 260 + kb + tig + 4];
        a[3] = Asu[(mbase + r + 8) * 260 + kb + tig + 4];
        #pragma unroll
        for (int nt = 0; nt < 8; nt++) {
            unsigned b[2];
            int ncol = nbase + nt * 8 + r;
            b[0] = Wcu[(kb + tig) * 136 + ncol];
            b[1] = Wcu[(kb + tig + 4) * 136 + ncol];
            mma_tf32(acc[nt], a, b);
        }
    }
    int node0 = base + mbase + r;
    int node1 = node0 + 8;
    #pragma unroll
    for (int nt = 0; nt < 8; nt++) {
        int col = nbase + nt * 8 + tig * 2;
        float b0 = bs[col], b1 = bs[col + 1];
        if (node0 < n) {
            float2 v = make_float2(tanhf(acc[nt][0] + b0), tanhf(acc[nt][1] + b1));
            *(float2*)((float*)g_h2 + node0 * 128 + col) = v;
        }
        if (node1 < n) {
            float2 v = make_float2(tanhf(acc[nt][2] + b0), tanhf(acc[nt][3] + b1));
            *(float2*)((float*)g_h2 + node1 * 128 + col) = v;
        }
    }
}

// ---------------- head: tf32 MMA t = tanh(h2@W1^T+b1); fp32 logits+softmax -
// Tile 64 nodes x 256 ch, K=128. Warp = m16 x n128 (16 n-tiles).
__global__ __launch_bounds__(256) void k_head(const float* __restrict__ W1,
        const float* __restrict__ b1, const float* __restrict__ W2,
        const float* __restrict__ b2, float* __restrict__ out, int n) {
    extern __shared__ float sm[];
    float* W1s = sm;                   // [128][264] tf32, k-major
    float* As  = W1s + 128 * 264;      // [64][132] tf32
    float* W2s = As + 64 * 132;        // [8][256] fp32
    float* b1s = W2s + 2048;           // [256]
    float* b2s = b1s + 256;            // [8]
    unsigned* W1u = (unsigned*)W1s;
    unsigned* Asu = (unsigned*)As;
    int tid = threadIdx.x;
    for (int idx = tid; idx < 256 * 128; idx += 256) {
        int c = idx >> 7;
        int k = idx & 127;
        W1u[k * 264 + c] = tf32u(W1[c * 128 + k]);
    }
    for (int idx = tid; idx < 2048; idx += 256) W2s[idx] = W2[idx];
    b1s[tid] = b1[tid];
    if (tid < 8) b2s[tid] = b2[tid];
    int base = blockIdx.x * 64;
    for (int f = tid; f < 64 * 32; f += 256) {
        int nl = f >> 5, kq = f & 31;
        int node = base + nl;
        float4 v = make_float4(0.f, 0.f, 0.f, 0.f);
        if (node < n) v = g_h2[node * 32 + kq];
        uint4 u = make_uint4(tf32u(v.x), tf32u(v.y), tf32u(v.z), tf32u(v.w));
        *(uint4*)(Asu + nl * 132 + kq * 4) = u;
    }
    __syncthreads();
    int warp = tid >> 5, lane = tid & 31;
    int r = lane >> 2, tig = lane & 3;
    int mbase = (warp & 3) * 16;
    int nbase = (warp >> 2) * 128;
    float acc[16][4];
    #pragma unroll
    for (int a = 0; a < 16; a++) { acc[a][0] = acc[a][1] = acc[a][2] = acc[a][3] = 0.f; }
    for (int kb = 0; kb < 128; kb += 8) {
        unsigned a[4];
        a[0] = Asu[(mbase + r) * 132 + kb + tig];
        a[1] = Asu[(mbase + r + 8) * 132 + kb + tig];
        a[2] = Asu[(mbase + r) * 132 + kb + tig + 4];
        a[3] = Asu[(mbase + r + 8) * 132 + kb + tig + 4];
        #pragma unroll
        for (int nt = 0; nt < 16; nt++) {
            unsigned b[2];
            int ncol = nbase + nt * 8 + r;
            b[0] = W1u[(kb + tig) * 264 + ncol];
            b[1] = W1u[(kb + tig + 4) * 264 + ncol];
            mma_tf32(acc[nt], a, b);
        }
    }
    // tanh + second layer partial logits (thread covers 32 of 256 channels
    // for rows node0/node1; quad (tig 0..3) covers the 128-col half; the two
    // warp n-halves are summed via the same quad reduction? No — halves are
    // different warps, so each warp's p is partial over its 128 cols; the
    // OTHER half is handled by the warp with same mbase, other nbase.
    // Cross-warp combine goes through shared memory.
    float p0[8], p1[8];
    #pragma unroll
    for (int c = 0; c < 8; c++) { p0[c] = 0.f; p1[c] = 0.f; }
    #pragma unroll
    for (int nt = 0; nt < 16; nt++) {
        int col = nbase + nt * 8 + tig * 2;
        float t00 = tanhf(acc[nt][0] + b1s[col]);
        float t01 = tanhf(acc[nt][1] + b1s[col + 1]);
        float t10 = tanhf(acc[nt][2] + b1s[col]);
        float t11 = tanhf(acc[nt][3] + b1s[col + 1]);
        #pragma unroll
        for (int c = 0; c < 8; c++) {
            float w0 = W2s[c * 256 + col], w1 = W2s[c * 256 + col + 1];
            p0[c] += t00 * w0 + t01 * w1;
            p1[c] += t10 * w0 + t11 * w1;
        }
    }
    // reduce across the quad (tig): lanes r*4 .. r*4+3 share rows
    #pragma unroll
    for (int o = 1; o <= 2; o <<= 1) {
        #pragma unroll
        for (int c = 0; c < 8; c++) {
            p0[c] += __shfl_xor_sync(0xffffffffu, p0[c], o);
            p1[c] += __shfl_xor_sync(0xffffffffu, p1[c], o);
        }
    }
    // combine the two n-halves (warps w and w+4) via smem, then softmax.
    // reuse As region as scratch: [64 rows][16 floats] per half -> [64][32]
    float* red = As;   // 64*32 floats, safe: As no longer needed
    __syncthreads();
    if (tig == 0) {
        int half = warp >> 2;
        float* dst0 = red + (mbase + r) * 32 + half * 16;
        float* dst1 = red + (mbase + r + 8) * 32 + half * 16;
        #pragma unroll
        for (int c = 0; c < 8; c++) { dst0[c] = p0[c]; dst1[c] = p1[c]; }
    }
    __syncthreads();
    // 64 nodes, 64 lanes-worth of work: threads 0..63 each do one node
    if (tid < 64) {
        int node = base + tid;
        if (node < n) {
            float l[8], m = -finf();
            #pragma unroll
            for (int c = 0; c < 8; c++) {
                l[c] = red[tid * 32 + c] + red[tid * 32 + 16 + c] + b2s[c];
                m = fmaxf(m, l[c]);
            }
            float s = 0.f;
            #pragma unroll
            for (int c = 0; c < 8; c++) { l[c] = expf(l[c] - m); s += l[c]; }
            float inv = 1.0f / s;
            float4 o0 = make_float4(l[0] * inv, l[1] * inv, l[2] * inv, l[3] * inv);
            float4 o1 = make_float4(l[4] * inv, l[5] * inv, l[6] * inv, l[7] * inv);
            *(float4*)(out + node * 8) = o0;
            *(float4*)(out + node * 8 + 4) = o1;
        }
    }
}

// ---------------- launch ---------------------------------------------------
extern "C" void kernel_launch(void* const* d_in, const int* in_sizes, int n_in,
                              void* d_out, int out_size) {
    const float* x = 0; const int* ei = 0;
    const float *Wl1 = 0, *bl1 = 0, *Wr1 = 0, *Wl2 = 0, *bl2 = 0, *Wr2 = 0;
    const float *W1 = 0, *b1 = 0, *W2 = 0, *b2 = 0;
    int n = 100000, nE = 600000;
    for (int i = 0; i < n_in; i++) {
        int sz = in_sizes[i];
        const void* p = d_in[i];
        switch (sz) {
            case 300000:  x  = (const float*)p; n  = sz / 3; break;
            case 1200000: ei = (const int*)p; nE = sz / 2; break;
            case 384:     if (!Wl1) Wl1 = (const float*)p; else Wr1 = (const float*)p; break;
            case 128:     if (!bl1) bl1 = (const float*)p; else bl2 = (const float*)p; break;
            case 16384:   if (!Wl2) Wl2 = (const float*)p; else Wr2 = (const float*)p; break;
            case 32768:   W1 = (const float*)p; break;
            case 256:     b1 = (const float*)p; break;
            case 2048:    W2 = (const float*)p; break;
            case 8:       b2 = (const float*)p; break;
            default: break;
        }
    }
    float* out = (float*)d_out;
    if (n > NMAX) n = NMAX;

    const int SMEM_CONV2 = (256 * 136 + 64 * 260 + 128) * 4;                 // 206336 B
    const int SMEM_HEAD  = (128 * 264 + 64 * 132 + 2048 + 256 + 8) * 4;      // 178208 B
    cudaFuncSetAttribute(k_conv2, cudaFuncAttributeMaxDynamicSharedMemorySize, SMEM_CONV2);
    cudaFuncSetAttribute(k_head,  cudaFuncAttributeMaxDynamicSharedMemorySize, SMEM_HEAD);

    k_detect<<<1, 32>>>(ei);
    k_init<<<(n * 32 + 255) / 256, 256>>>(n);
    int nb = (n + 255) / 256;
    k_stats1<<<nb, 256>>>(x, n);
    k_rot<<<nb, 256>>>(x, n);
    k_norm<<<nb, 256>>>(n);
    k_agg1<<<(nE + 255) / 256, 256>>>(ei, nE, n);
    k_conv1<<<(n + 1) / 2, 256>>>(Wl1, bl1, Wr1, n);
    k_agg2<<<(nE + 7) / 8, 256>>>(ei, nE, n);
    k_conv2<<<(n + 63) / 64, 256, SMEM_CONV2>>>(Wl2, bl2, Wr2, n);
    k_head<<<(n + 63) / 64, 256, SMEM_HEAD>>>(W1, b1, W2, b2, out, n);
}

// round 10
// speedup vs baseline: 1.5715x; 1.0091x over previous
#include <cuda_runtime.h>
#include <math.h>

#define NMAX 100000
#define EMAX 600000
#define NBMAX 512

// ---------------- scratch (device globals: no allocation allowed) ----------
__device__ float4 g_h0[NMAX];           // normalized input features (x,y,area,0)
__device__ float4 g_agg0[NMAX];         // conv1 aggregate; .w = degree
__device__ float4 g_h1[NMAX * 32];      // conv1 output      [node][128]
__device__ float4 g_agg1[NMAX * 32];    // conv2 mean-aggregate [node][128]
__device__ float4 g_h2[NMAX * 32];      // conv2 output      [node][128]
__device__ int    g_cnt[NMAX];          // per-dst counts / fill cursors
__device__ int    g_tmp[NMAX];          // block-local exclusive prefix
__device__ int    g_bsum[NBMAX];        // per-block totals
__device__ int    g_boff[NBMAX];        // per-block offsets
__device__ int    g_rowptr[NMAX + 1];   // CSR row pointers (by destination)
__device__ int    g_elist[EMAX];        // CSR column list: source node ids
__device__ float    g_stats[8];         // sums for _normalize
__device__ unsigned g_statu[8];         // encoded min/max
__device__ int    g_ei64;               // 1 if edge_index is int64, 0 if int32

__device__ __forceinline__ float finf() { return __int_as_float(0x7f800000); }

// order-preserving float<->uint encode (atomicMin/Max on unsigned == float order)
__device__ __forceinline__ unsigned fenc(float f) {
    unsigned u = __float_as_uint(f);
    return u ^ ((unsigned)((int)u >> 31) | 0x80000000u);
}
__device__ __forceinline__ float fdec(unsigned e) {
    unsigned u = (e & 0x80000000u) ? (e ^ 0x80000000u) : ~e;
    return __uint_as_float(u);
}

// fp32 -> tf32 bit pattern (round-to-nearest, keeps 10 mantissa bits)
__device__ __forceinline__ unsigned tf32u(float f) {
    unsigned r;
    asm("cvt.rna.tf32.f32 %0, %1;" : "=r"(r) : "f"(f));
    return r;
}

// m16n8k8 tf32 MMA, fp32 accumulate
__device__ __forceinline__ void mma_tf32(float* c, const unsigned* a, const unsigned* b) {
    asm volatile("mma.sync.aligned.m16n8k8.row.col.f32.tf32.tf32.f32 "
        "{%0,%1,%2,%3}, {%4,%5,%6,%7}, {%8,%9}, {%0,%1,%2,%3};"
        : "+f"(c[0]), "+f"(c[1]), "+f"(c[2]), "+f"(c[3])
        : "r"(a[0]), "r"(a[1]), "r"(a[2]), "r"(a[3]), "r"(b[0]), "r"(b[1]));
}

// Fetch edge endpoint #i from a buffer of unknown (int32 vs int64) dtype.
__device__ __forceinline__ int edge_at(const int* ei32, int i) {
    return g_ei64 ? (int)((const long long*)ei32)[i] : ei32[i];
}

// ---------------- init: zero counters, reset stats, probe edge dtype -------
__global__ void k_init(const int* __restrict__ ei32, int n) {
    int i = blockIdx.x * blockDim.x + threadIdx.x;
    if (i < n) g_cnt[i] = 0;
    if (i == 0) {
        g_statu[0] = 0xFFFFFFFFu; g_statu[1] = 0u;   // min/max x0
        g_statu[2] = 0xFFFFFFFFu; g_statu[3] = 0u;   // min/max x1
        g_statu[4] = 0u;                              // max area
        g_statu[5] = 0u; g_statu[6] = 0u;             // max r0, r1
        g_stats[0] = 0.f; g_stats[1] = 0.f;           // sum r0, sum r1
        int acc = 0;
        #pragma unroll
        for (int j = 0; j < 128; j++) acc |= ei32[2 * j + 1];
        g_ei64 = (acc == 0) ? 1 : 0;                  // int64 => high words zero
    }
}

// ---------------- CSR build: count / scan / fill ---------------------------
__global__ void k_count(const int* __restrict__ ei, int nE, int n) {
    int i = blockIdx.x * blockDim.x + threadIdx.x;
    if (i >= nE) return;
    int d = edge_at(ei, nE + i);
    d = min(max(d, 0), n - 1);
    atomicAdd(&g_cnt[d], 1);
}

__global__ void k_scan1(int n) {
    __shared__ int sm[256];
    int t = threadIdx.x;
    int i = blockIdx.x * 256 + t;
    int v = (i < n) ? g_cnt[i] : 0;
    sm[t] = v; __syncthreads();
    for (int o = 1; o < 256; o <<= 1) {
        int u = (t >= o) ? sm[t - o] : 0;
        __syncthreads();
        sm[t] += u;
        __syncthreads();
    }
    if (i < n) g_tmp[i] = sm[t] - v;          // block-local exclusive
    if (t == 255) g_bsum[blockIdx.x] = sm[255];
}

__global__ void k_scan2(int nb, int n) {
    __shared__ int sm[NBMAX];
    int t = threadIdx.x;
    int v = (t < nb) ? g_bsum[t] : 0;
    sm[t] = v; __syncthreads();
    for (int o = 1; o < NBMAX; o <<= 1) {
        int u = (t >= o) ? sm[t - o] : 0;
        __syncthreads();
        sm[t] += u;
        __syncthreads();
    }
    if (t < nb) g_boff[t] = sm[t] - v;        // exclusive block offsets
    if (t == nb - 1) g_rowptr[n] = sm[t];     // grand total
}

__global__ void k_scan3(int n) {
    int i = blockIdx.x * blockDim.x + threadIdx.x;
    if (i >= n) return;
    g_rowptr[i] = g_tmp[i] + g_boff[blockIdx.x];
    g_cnt[i] = 0;                              // reuse as fill cursor
}

__global__ void k_fill(const int* __restrict__ ei, int nE, int n) {
    int i = blockIdx.x * blockDim.x + threadIdx.x;
    if (i >= nE) return;
    int s = edge_at(ei, i);
    int d = edge_at(ei, nE + i);
    s = min(max(s, 0), n - 1);
    d = min(max(d, 0), n - 1);
    int pos = atomicAdd(&g_cnt[d], 1);
    g_elist[g_rowptr[d] + pos] = s;
}

// ---------------- normalize pass 1: min/max of raw coords, max area --------
__global__ void k_stats1(const float* __restrict__ x, int n) {
    int i = blockIdx.x * blockDim.x + threadIdx.x;
    float mn0 = finf(), mx0 = -finf(), mn1 = finf(), mx1 = -finf(), mxA = -finf();
    if (i < n) {
        float a = x[3 * i], b = x[3 * i + 1], c = x[3 * i + 2];
        mn0 = mx0 = a; mn1 = mx1 = b; mxA = c;
    }
    #pragma unroll
    for (int o = 16; o; o >>= 1) {
        mn0 = fminf(mn0, __shfl_xor_sync(0xffffffffu, mn0, o));
        mx0 = fmaxf(mx0, __shfl_xor_sync(0xffffffffu, mx0, o));
        mn1 = fminf(mn1, __shfl_xor_sync(0xffffffffu, mn1, o));
        mx1 = fmaxf(mx1, __shfl_xor_sync(0xffffffffu, mx1, o));
        mxA = fmaxf(mxA, __shfl_xor_sync(0xffffffffu, mxA, o));
    }
    if ((threadIdx.x & 31) == 0) {
        atomicMin(&g_statu[0], fenc(mn0)); atomicMax(&g_statu[1], fenc(mx0));
        atomicMin(&g_statu[2], fenc(mn1)); atomicMax(&g_statu[3], fenc(mx1));
        atomicMax(&g_statu[4], fenc(mxA));
    }
}

// ---------------- normalize pass 2: (conditionally) rotate, sum & max ------
__global__ void k_rot(const float* __restrict__ x, int n) {
    int i = blockIdx.x * blockDim.x + threadIdx.x;
    bool rot = (fdec(g_statu[3]) - fdec(g_statu[2])) > (fdec(g_statu[1]) - fdec(g_statu[0]));
    float s0 = 0.f, s1 = 0.f, m0 = -finf(), m1 = -finf();
    if (i < n) {
        float a = x[3 * i], b = x[3 * i + 1], ar = x[3 * i + 2];
        float cc = cosf(1.5707964f);   // cos(float32(pi/2)) as jax computes it
        float ss = sinf(1.5707964f);
        float r0 = rot ? (cc * a - ss * b) : a;
        float r1 = rot ? (ss * a + cc * b) : b;
        g_h0[i] = make_float4(r0, r1, ar, 0.f);
        s0 = r0; s1 = r1; m0 = r0; m1 = r1;
    }
    #pragma unroll
    for (int o = 16; o; o >>= 1) {
        s0 += __shfl_xor_sync(0xffffffffu, s0, o);
        s1 += __shfl_xor_sync(0xffffffffu, s1, o);
        m0 = fmaxf(m0, __shfl_xor_sync(0xffffffffu, m0, o));
        m1 = fmaxf(m1, __shfl_xor_sync(0xffffffffu, m1, o));
    }
    if ((threadIdx.x & 31) == 0) {
        atomicAdd(&g_stats[0], s0); atomicAdd(&g_stats[1], s1);
        atomicMax(&g_statu[5], fenc(m0)); atomicMax(&g_statu[6], fenc(m1));
    }
}

// ---------------- normalize pass 3: center/scale ---------------------------
__global__ void k_norm(int n) {
    int i = blockIdx.x * blockDim.x + threadIdx.x;
    if (i >= n) return;
    float me0 = g_stats[0] / (float)n;
    float me1 = g_stats[1] / (float)n;
    float4 v = g_h0[i];
    v.x = (v.x - me0) / fdec(g_statu[5]);
    v.y = (v.y - me1) / fdec(g_statu[6]);
    v.z = v.z / fdec(g_statu[4]);
    v.w = 0.f;
    g_h0[i] = v;
}

// ---------------- conv1 aggregate: CSR gather, thread per node -------------
__global__ void k_aggc1(int n) {
    int i = blockIdx.x * blockDim.x + threadIdx.x;
    if (i >= n) return;
    int beg = g_rowptr[i], end = g_rowptr[i + 1];
    float sx = 0.f, sy = 0.f, sz = 0.f;
    for (int j = beg; j < end; j++) {
        int s = g_elist[j];
        float4 v = g_h0[s];
        sx += v.x; sy += v.y; sz += v.z;
    }
    g_agg0[i] = make_float4(sx, sy, sz, (float)(end - beg));
}

// ---------------- conv1 compute: h1 = tanh(Wl1*agg/deg + bl1 + Wr1*h0) -----
__global__ void k_conv1(const float* __restrict__ Wl, const float* __restrict__ bl,
                        const float* __restrict__ Wr, int n) {
    __shared__ float wl[384], wr[384], bb[128];
    int tid = threadIdx.x;
    if (tid < 128) bb[tid] = bl[tid];
    for (int j = tid; j < 384; j += blockDim.x) { wl[j] = Wl[j]; wr[j] = Wr[j]; }
    __syncthreads();
    int i = blockIdx.x * 2 + (tid >> 7);
    if (i >= n) return;
    int c = tid & 127;
    float4 ag = g_agg0[i];
    float inv = 1.0f / fmaxf(ag.w, 1.0f);
    float4 h = g_h0[i];
    float v = bb[c]
        + wl[c * 3 + 0] * (ag.x * inv) + wl[c * 3 + 1] * (ag.y * inv) + wl[c * 3 + 2] * (ag.z * inv)
        + wr[c * 3 + 0] * h.x + wr[c * 3 + 1] * h.y + wr[c * 3 + 2] * h.z;
    ((float*)g_h1)[i * 128 + c] = tanhf(v);
}

// ---------------- conv2 aggregate: warp per node, full occupancy -----------
// No smem, low regs => many warps/SM; the ~310MB of (mostly L2-resident)
// neighbor reads run at LTS throughput, latency hidden by warp parallelism.
// Mean (division by deg) fused here.
__global__ void k_aggc2(int n) {
    int node = blockIdx.x * 8 + (threadIdx.x >> 5);
    if (node >= n) return;
    int lane = threadIdx.x & 31;
    int beg = g_rowptr[node], end = g_rowptr[node + 1];
    int cnt = end - beg;
    float4 acc = make_float4(0.f, 0.f, 0.f, 0.f);
    for (int base = beg; base < end; base += 32) {
        int m = min(end - base, 32);
        int sv = (lane < m) ? g_elist[base + lane] : 0;
        for (int j = 0; j < m; j++) {
            int s = __shfl_sync(0xffffffffu, sv, j);
            float4 v = g_h1[s * 32 + lane];
            acc.x += v.x; acc.y += v.y; acc.z += v.z; acc.w += v.w;
        }
    }
    float inv = 1.0f / fmaxf((float)cnt, 1.0f);
    acc.x *= inv; acc.y *= inv; acc.z *= inv; acc.w *= inv;
    g_agg1[node * 32 + lane] = acc;
}

// ---------------- conv2: tf32 MMA GEMM, h2 = tanh([agg|h1]@W^T + b) --------
// Tile 64 nodes x 128 ch, K=256. Warp = m16 x n64. Smem strides padded for
// conflict-free fragment loads.
__global__ __launch_bounds__(256) void k_conv2(const float* __restrict__ Wl,
        const float* __restrict__ bl, const float* __restrict__ Wr, int n) {
    extern __shared__ float sm[];
    float* Wc = sm;                    // [256][136] tf32, k-major
    float* As = sm + 256 * 136;        // [64][260] tf32
    float* bs = As + 64 * 260;         // [128]
    unsigned* Wcu = (unsigned*)Wc;
    unsigned* Asu = (unsigned*)As;
    int tid = threadIdx.x;
    for (int idx = tid; idx < 128 * 256; idx += 256) {
        int c = idx >> 8;
        int k = idx & 255;
        float w = (k < 128) ? Wl[c * 128 + k] : Wr[c * 128 + (k - 128)];
        Wcu[k * 136 + c] = tf32u(w);
    }
    if (tid < 128) bs[tid] = bl[tid];
    int base = blockIdx.x * 64;
    for (int f = tid; f < 64 * 64; f += 256) {
        int nl = f >> 6;
        int kq = f & 63;
        int node = base + nl;
        float4 v = make_float4(0.f, 0.f, 0.f, 0.f);
        if (node < n)
            v = (kq < 32) ? g_agg1[node * 32 + kq] : g_h1[node * 32 + (kq - 32)];
        uint4 u = make_uint4(tf32u(v.x), tf32u(v.y), tf32u(v.z), tf32u(v.w));
        *(uint4*)(Asu + nl * 260 + kq * 4) = u;
    }
    __syncthreads();
    int warp = tid >> 5, lane = tid & 31;
    int r = lane >> 2, tig = lane & 3;
    int mbase = (warp & 3) * 16;
    int nbase = (warp >> 2) * 64;
    float acc[8][4];
    #pragma unroll
    for (int a = 0; a < 8; a++) { acc[a][0] = acc[a][1] = acc[a][2] = acc[a][3] = 0.f; }
    for (int kb = 0; kb < 256; kb += 8) {
        unsigned a[4];
        a[0] = Asu[(mbase + r) * 260 + kb + tig];
        a[1] = Asu[(mbase + r + 8) * 260 + kb + tig];
        a[2] = Asu[(mbase + r) * 260 + kb + tig + 4];
        a[3] = Asu[(mbase + r + 8) * 260 + kb + tig + 4];
        #pragma unroll
        for (int nt = 0; nt < 8; nt++) {
            unsigned b[2];
            int ncol = nbase + nt * 8 + r;
            b[0] = Wcu[(kb + tig) * 136 + ncol];
            b[1] = Wcu[(kb + tig + 4) * 136 + ncol];
            mma_tf32(acc[nt], a, b);
        }
    }
    int node0 = base + mbase + r;
    int node1 = node0 + 8;
    #pragma unroll
    for (int nt = 0; nt < 8; nt++) {
        int col = nbase + nt * 8 + tig * 2;
        float b0 = bs[col], b1 = bs[col + 1];
        if (node0 < n) {
            float2 v = make_float2(tanhf(acc[nt][0] + b0), tanhf(acc[nt][1] + b1));
            *(float2*)((float*)g_h2 + node0 * 128 + col) = v;
        }
        if (node1 < n) {
            float2 v = make_float2(tanhf(acc[nt][2] + b0), tanhf(acc[nt][3] + b1));
            *(float2*)((float*)g_h2 + node1 * 128 + col) = v;
        }
    }
}

// ---------------- head: tf32 MMA t = tanh(h2@W1^T+b1); fp32 logits+softmax -
__global__ __launch_bounds__(256) void k_head(const float* __restrict__ W1,
        const float* __restrict__ b1, const float* __restrict__ W2,
        const float* __restrict__ b2, float* __restrict__ out, int n) {
    extern __shared__ float sm[];
    float* W1s = sm;                   // [128][264] tf32, k-major
    float* As  = W1s + 128 * 264;      // [64][132] tf32
    float* W2s = As + 64 * 132;        // [8][256] fp32
    float* b1s = W2s + 2048;           // [256]
    float* b2s = b1s + 256;            // [8]
    unsigned* W1u = (unsigned*)W1s;
    unsigned* Asu = (unsigned*)As;
    int tid = threadIdx.x;
    for (int idx = tid; idx < 256 * 128; idx += 256) {
        int c = idx >> 7;
        int k = idx & 127;
        W1u[k * 264 + c] = tf32u(W1[c * 128 + k]);
    }
    for (int idx = tid; idx < 2048; idx += 256) W2s[idx] = W2[idx];
    b1s[tid] = b1[tid];
    if (tid < 8) b2s[tid] = b2[tid];
    int base = blockIdx.x * 64;
    for (int f = tid; f < 64 * 32; f += 256) {
        int nl = f >> 5, kq = f & 31;
        int node = base + nl;
        float4 v = make_float4(0.f, 0.f, 0.f, 0.f);
        if (node < n) v = g_h2[node * 32 + kq];
        uint4 u = make_uint4(tf32u(v.x), tf32u(v.y), tf32u(v.z), tf32u(v.w));
        *(uint4*)(Asu + nl * 132 + kq * 4) = u;
    }
    __syncthreads();
    int warp = tid >> 5, lane = tid & 31;
    int r = lane >> 2, tig = lane & 3;
    int mbase = (warp & 3) * 16;
    int nbase = (warp >> 2) * 128;
    float acc[16][4];
    #pragma unroll
    for (int a = 0; a < 16; a++) { acc[a][0] = acc[a][1] = acc[a][2] = acc[a][3] = 0.f; }
    for (int kb = 0; kb < 128; kb += 8) {
        unsigned a[4];
        a[0] = Asu[(mbase + r) * 132 + kb + tig];
        a[1] = Asu[(mbase + r + 8) * 132 + kb + tig];
        a[2] = Asu[(mbase + r) * 132 + kb + tig + 4];
        a[3] = Asu[(mbase + r + 8) * 132 + kb + tig + 4];
        #pragma unroll
        for (int nt = 0; nt < 16; nt++) {
            unsigned b[2];
            int ncol = nbase + nt * 8 + r;
            b[0] = W1u[(kb + tig) * 264 + ncol];
            b[1] = W1u[(kb + tig + 4) * 264 + ncol];
            mma_tf32(acc[nt], a, b);
        }
    }
    // tanh + second layer partial logits; quad covers this warp's 128-col
    // half; the other half lives in warp (w xor 4); combine via smem.
    float p0[8], p1[8];
    #pragma unroll
    for (int c = 0; c < 8; c++) { p0[c] = 0.f; p1[c] = 0.f; }
    #pragma unroll
    for (int nt = 0; nt < 16; nt++) {
        int col = nbase + nt * 8 + tig * 2;
        float t00 = tanhf(acc[nt][0] + b1s[col]);
        float t01 = tanhf(acc[nt][1] + b1s[col + 1]);
        float t10 = tanhf(acc[nt][2] + b1s[col]);
        float t11 = tanhf(acc[nt][3] + b1s[col + 1]);
        #pragma unroll
        for (int c = 0; c < 8; c++) {
            float w0 = W2s[c * 256 + col], w1 = W2s[c * 256 + col + 1];
            p0[c] += t00 * w0 + t01 * w1;
            p1[c] += t10 * w0 + t11 * w1;
        }
    }
    #pragma unroll
    for (int o = 1; o <= 2; o <<= 1) {
        #pragma unroll
        for (int c = 0; c < 8; c++) {
            p0[c] += __shfl_xor_sync(0xffffffffu, p0[c], o);
            p1[c] += __shfl_xor_sync(0xffffffffu, p1[c], o);
        }
    }
    float* red = As;   // reuse As as [64][32] scratch (no longer needed)
    __syncthreads();
    if (tig == 0) {
        int half = warp >> 2;
        float* dst0 = red + (mbase + r) * 32 + half * 16;
        float* dst1 = red + (mbase + r + 8) * 32 + half * 16;
        #pragma unroll
        for (int c = 0; c < 8; c++) { dst0[c] = p0[c]; dst1[c] = p1[c]; }
    }
    __syncthreads();
    if (tid < 64) {
        int node = base + tid;
        if (node < n) {
            float l[8], m = -finf();
            #pragma unroll
            for (int c = 0; c < 8; c++) {
                l[c] = red[tid * 32 + c] + red[tid * 32 + 16 + c] + b2s[c];
                m = fmaxf(m, l[c]);
            }
            float s = 0.f;
            #pragma unroll
            for (int c = 0; c < 8; c++) { l[c] = expf(l[c] - m); s += l[c]; }
            float inv = 1.0f / s;
            float4 o0 = make_float4(l[0] * inv, l[1] * inv, l[2] * inv, l[3] * inv);
            float4 o1 = make_float4(l[4] * inv, l[5] * inv, l[6] * inv, l[7] * inv);
            *(float4*)(out + node * 8) = o0;
            *(float4*)(out + node * 8 + 4) = o1;
        }
    }
}

// ---------------- launch ---------------------------------------------------
extern "C" void kernel_launch(void* const* d_in, const int* in_sizes, int n_in,
                              void* d_out, int out_size) {
    const float* x = 0; const int* ei = 0;
    const float *Wl1 = 0, *bl1 = 0, *Wr1 = 0, *Wl2 = 0, *bl2 = 0, *Wr2 = 0;
    const float *W1 = 0, *b1 = 0, *W2 = 0, *b2 = 0;
    int n = 100000, nE = 600000;
    for (int i = 0; i < n_in; i++) {
        int sz = in_sizes[i];
        const void* p = d_in[i];
        switch (sz) {
            case 300000:  x  = (const float*)p; n  = sz / 3; break;
            case 1200000: ei = (const int*)p; nE = sz / 2; break;
            case 384:     if (!Wl1) Wl1 = (const float*)p; else Wr1 = (const float*)p; break;
            case 128:     if (!bl1) bl1 = (const float*)p; else bl2 = (const float*)p; break;
            case 16384:   if (!Wl2) Wl2 = (const float*)p; else Wr2 = (const float*)p; break;
            case 32768:   W1 = (const float*)p; break;
            case 256:     b1 = (const float*)p; break;
            case 2048:    W2 = (const float*)p; break;
            case 8:       b2 = (const float*)p; break;
            default: break;
        }
    }
    float* out = (float*)d_out;
    if (n > NMAX) n = NMAX;
    if (nE > EMAX) nE = EMAX;

    const int SMEM_CONV2 = (256 * 136 + 64 * 260 + 128) * 4;                 // 206336 B
    const int SMEM_HEAD  = (128 * 264 + 64 * 132 + 2048 + 256 + 8) * 4;      // 178208 B
    cudaFuncSetAttribute(k_conv2, cudaFuncAttributeMaxDynamicSharedMemorySize, SMEM_CONV2);
    cudaFuncSetAttribute(k_head,  cudaFuncAttributeMaxDynamicSharedMemorySize, SMEM_HEAD);

    int nb = (n + 255) / 256;
    int eb = (nE + 255) / 256;
    k_init<<<nb, 256>>>(ei, n);
    k_count<<<eb, 256>>>(ei, nE, n);
    k_scan1<<<nb, 256>>>(n);
    k_scan2<<<1, NBMAX>>>(nb, n);
    k_scan3<<<nb, 256>>>(n);
    k_fill<<<eb, 256>>>(ei, nE, n);
    k_stats1<<<nb, 256>>>(x, n);
    k_rot<<<nb, 256>>>(x, n);
    k_norm<<<nb, 256>>>(n);
    k_aggc1<<<nb, 256>>>(n);
    k_conv1<<<(n + 1) / 2, 256>>>(Wl1, bl1, Wr1, n);
    k_aggc2<<<(n + 7) / 8, 256>>>(n);
    k_conv2<<<(n + 63) / 64, 256, SMEM_CONV2>>>(Wl2, bl2, Wr2, n);
    k_head<<<(n + 63) / 64, 256, SMEM_HEAD>>>(W1, b1, W2, b2, out, n);
}

// round 12
// speedup vs baseline: 2.1800x; 1.3872x over previous
#include <cuda_runtime.h>
#include <math.h>

#define NMAX 100000
#define EMAX 600000
#define NBMAX 512

// ---------------- scratch (device globals: no allocation allowed) ----------
__device__ float4 g_h0[NMAX];           // rotated (NOT normalized) features
__device__ float4 g_agg0[NMAX];         // conv1 raw aggregate; .w = degree
__device__ float4 g_h1[NMAX * 32];      // conv1 output      [node][128]
__device__ float4 g_agg1[NMAX * 32];    // conv2 mean-aggregate [node][128]
__device__ float4 g_h2[NMAX * 32];      // conv2 output      [node][128]
__device__ int    g_cnt[NMAX];          // per-dst counts / fill cursors
__device__ int    g_tmp[NMAX];          // block-local exclusive prefix
__device__ int    g_bsum[NBMAX];        // per-block totals
__device__ int    g_boff[NBMAX];        // per-block offsets
__device__ int    g_rowptr[NMAX + 1];   // CSR row pointers (by destination)
__device__ int    g_elist[EMAX];        // CSR column list: source node ids
__device__ float    g_stats[8];         // sums for _normalize
__device__ unsigned g_statu[8];         // encoded min/max
__device__ int    g_ei64;               // 1 if edge_index is int64, 0 if int32

__device__ __forceinline__ float finf() { return __int_as_float(0x7f800000); }

__device__ __forceinline__ unsigned fenc(float f) {
    unsigned u = __float_as_uint(f);
    return u ^ ((unsigned)((int)u >> 31) | 0x80000000u);
}
__device__ __forceinline__ float fdec(unsigned e) {
    unsigned u = (e & 0x80000000u) ? (e ^ 0x80000000u) : ~e;
    return __uint_as_float(u);
}

__device__ __forceinline__ unsigned tf32u(float f) {
    unsigned r;
    asm("cvt.rna.tf32.f32 %0, %1;" : "=r"(r) : "f"(f));
    return r;
}

__device__ __forceinline__ void mma_tf32(float* c, const unsigned* a, const unsigned* b) {
    asm volatile("mma.sync.aligned.m16n8k8.row.col.f32.tf32.tf32.f32 "
        "{%0,%1,%2,%3}, {%4,%5,%6,%7}, {%8,%9}, {%0,%1,%2,%3};"
        : "+f"(c[0]), "+f"(c[1]), "+f"(c[2]), "+f"(c[3])
        : "r"(a[0]), "r"(a[1]), "r"(a[2]), "r"(a[3]), "r"(b[0]), "r"(b[1]));
}

__device__ __forceinline__ int edge_at(const int* ei32, int i) {
    return g_ei64 ? (int)((const long long*)ei32)[i] : ei32[i];
}

// ---------------- init: zero counters, reset stats, probe edge dtype -------
__global__ void k_init(const int* __restrict__ ei32, int n) {
    int i = blockIdx.x * blockDim.x + threadIdx.x;
    if (i < n) g_cnt[i] = 0;
    if (i == 0) {
        g_statu[0] = 0xFFFFFFFFu; g_statu[1] = 0u;
        g_statu[2] = 0xFFFFFFFFu; g_statu[3] = 0u;
        g_statu[4] = 0u;
        g_statu[5] = 0u; g_statu[6] = 0u;
        g_stats[0] = 0.f; g_stats[1] = 0.f;
        int acc = 0;
        #pragma unroll
        for (int j = 0; j < 128; j++) acc |= ei32[2 * j + 1];
        g_ei64 = (acc == 0) ? 1 : 0;
    }
}

// ---------------- CSR build: count / scan / fill ---------------------------
__global__ void k_count(const int* __restrict__ ei, int nE, int n) {
    int i = blockIdx.x * blockDim.x + threadIdx.x;
    if (i >= nE) return;
    int d = edge_at(ei, nE + i);
    d = min(max(d, 0), n - 1);
    atomicAdd(&g_cnt[d], 1);
}

__global__ void k_scan1(int n) {
    __shared__ int sm[256];
    int t = threadIdx.x;
    int i = blockIdx.x * 256 + t;
    int v = (i < n) ? g_cnt[i] : 0;
    sm[t] = v; __syncthreads();
    for (int o = 1; o < 256; o <<= 1) {
        int u = (t >= o) ? sm[t - o] : 0;
        __syncthreads();
        sm[t] += u;
        __syncthreads();
    }
    if (i < n) g_tmp[i] = sm[t] - v;
    if (t == 255) g_bsum[blockIdx.x] = sm[255];
}

__global__ void k_scan2(int nb, int n) {
    __shared__ int sm[NBMAX];
    int t = threadIdx.x;
    int v = (t < nb) ? g_bsum[t] : 0;
    sm[t] = v; __syncthreads();
    for (int o = 1; o < NBMAX; o <<= 1) {
        int u = (t >= o) ? sm[t - o] : 0;
        __syncthreads();
        sm[t] += u;
        __syncthreads();
    }
    if (t < nb) g_boff[t] = sm[t] - v;
    if (t == nb - 1) g_rowptr[n] = sm[t];
}

__global__ void k_scan3(int n) {
    int i = blockIdx.x * blockDim.x + threadIdx.x;
    if (i >= n) return;
    g_rowptr[i] = g_tmp[i] + g_boff[blockIdx.x];
    g_cnt[i] = 0;
}

__global__ void k_fill(const int* __restrict__ ei, int nE, int n) {
    int i = blockIdx.x * blockDim.x + threadIdx.x;
    if (i >= nE) return;
    int s = edge_at(ei, i);
    int d = edge_at(ei, nE + i);
    s = min(max(s, 0), n - 1);
    d = min(max(d, 0), n - 1);
    int pos = atomicAdd(&g_cnt[d], 1);
    g_elist[g_rowptr[d] + pos] = s;
}

// ---------------- normalize pass 1: min/max of raw coords, max area --------
__global__ void k_stats1(const float* __restrict__ x, int n) {
    int i = blockIdx.x * blockDim.x + threadIdx.x;
    float mn0 = finf(), mx0 = -finf(), mn1 = finf(), mx1 = -finf(), mxA = -finf();
    if (i < n) {
        float a = x[3 * i], b = x[3 * i + 1], c = x[3 * i + 2];
        mn0 = mx0 = a; mn1 = mx1 = b; mxA = c;
    }
    #pragma unroll
    for (int o = 16; o; o >>= 1) {
        mn0 = fminf(mn0, __shfl_xor_sync(0xffffffffu, mn0, o));
        mx0 = fmaxf(mx0, __shfl_xor_sync(0xffffffffu, mx0, o));
        mn1 = fminf(mn1, __shfl_xor_sync(0xffffffffu, mn1, o));
        mx1 = fmaxf(mx1, __shfl_xor_sync(0xffffffffu, mx1, o));
        mxA = fmaxf(mxA, __shfl_xor_sync(0xffffffffu, mxA, o));
    }
    if ((threadIdx.x & 31) == 0) {
        atomicMin(&g_statu[0], fenc(mn0)); atomicMax(&g_statu[1], fenc(mx0));
        atomicMin(&g_statu[2], fenc(mn1)); atomicMax(&g_statu[3], fenc(mx1));
        atomicMax(&g_statu[4], fenc(mxA));
    }
}

// ---------------- normalize pass 2: (conditionally) rotate, sum & max ------
// Writes ROTATED (not yet centered/scaled) h0; normalization is affine and is
// folded into conv1.
__global__ void k_rot(const float* __restrict__ x, int n) {
    int i = blockIdx.x * blockDim.x + threadIdx.x;
    bool rot = (fdec(g_statu[3]) - fdec(g_statu[2])) > (fdec(g_statu[1]) - fdec(g_statu[0]));
    float s0 = 0.f, s1 = 0.f, m0 = -finf(), m1 = -finf();
    if (i < n) {
        float a = x[3 * i], b = x[3 * i + 1], ar = x[3 * i + 2];
        float cc = cosf(1.5707964f);
        float ss = sinf(1.5707964f);
        float r0 = rot ? (cc * a - ss * b) : a;
        float r1 = rot ? (ss * a + cc * b) : b;
        g_h0[i] = make_float4(r0, r1, ar, 0.f);
        s0 = r0; s1 = r1; m0 = r0; m1 = r1;
    }
    #pragma unroll
    for (int o = 16; o; o >>= 1) {
        s0 += __shfl_xor_sync(0xffffffffu, s0, o);
        s1 += __shfl_xor_sync(0xffffffffu, s1, o);
        m0 = fmaxf(m0, __shfl_xor_sync(0xffffffffu, m0, o));
        m1 = fmaxf(m1, __shfl_xor_sync(0xffffffffu, m1, o));
    }
    if ((threadIdx.x & 31) == 0) {
        atomicAdd(&g_stats[0], s0); atomicAdd(&g_stats[1], s1);
        atomicMax(&g_statu[5], fenc(m0)); atomicMax(&g_statu[6], fenc(m1));
    }
}

// ---------------- conv1 aggregate: CSR gather of RAW rotated h0 ------------
__global__ void k_aggc1(int n) {
    int i = blockIdx.x * blockDim.x + threadIdx.x;
    if (i >= n) return;
    int beg = g_rowptr[i], end = g_rowptr[i + 1];
    float sx = 0.f, sy = 0.f, sz = 0.f;
    for (int j = beg; j < end; j++) {
        int s = g_elist[j];
        float4 v = g_h0[s];
        sx += v.x; sy += v.y; sz += v.z;
    }
    g_agg0[i] = make_float4(sx, sy, sz, (float)(end - beg));
}

// ---------------- conv1: h1 = tanh(Wl1*norm(agg)/deg + bl1 + Wr1*norm(h0)) -
// Normalization folded in: norm(v) = ((vx-me0)/s0, (vy-me1)/s1, vz/sA).
// agg of normalized = (Σ - cnt*mean)/scale; then / deg.
__global__ void k_conv1(const float* __restrict__ Wl, const float* __restrict__ bl,
                        const float* __restrict__ Wr, int n) {
    __shared__ float wl[384], wr[384], bb[128];
    int tid = threadIdx.x;
    if (tid < 128) bb[tid] = bl[tid];
    for (int j = tid; j < 384; j += blockDim.x) { wl[j] = Wl[j]; wr[j] = Wr[j]; }
    __syncthreads();
    float me0 = g_stats[0] / (float)n;
    float me1 = g_stats[1] / (float)n;
    float sc0 = fdec(g_statu[5]);
    float sc1 = fdec(g_statu[6]);
    float scA = fdec(g_statu[4]);
    int c = tid & 127;
    float wl0 = wl[c * 3 + 0], wl1 = wl[c * 3 + 1], wl2 = wl[c * 3 + 2];
    float wr0 = wr[c * 3 + 0], wr1 = wr[c * 3 + 1], wr2 = wr[c * 3 + 2];
    float bc = bb[c];
    #pragma unroll
    for (int q = 0; q < 8; q++) {
        int i = blockIdx.x * 16 + q * 2 + (tid >> 7);
        if (i >= n) continue;
        float4 ag = g_agg0[i];
        float cnt = ag.w;
        float invd = 1.0f / fmaxf(cnt, 1.0f);
        float ax = (ag.x - cnt * me0) / sc0 * invd;
        float ay = (ag.y - cnt * me1) / sc1 * invd;
        float az = ag.z / scA * invd;
        float4 h = g_h0[i];
        float nx = (h.x - me0) / sc0;
        float ny = (h.y - me1) / sc1;
        float nz = h.z / scA;
        float v = bc + wl0 * ax + wl1 * ay + wl2 * az
                     + wr0 * nx + wr1 * ny + wr2 * nz;
        ((float*)g_h1)[i * 128 + c] = tanhf(v);
    }
}

// ---------------- conv2 aggregate: warp per node ---------------------------
__global__ void k_aggc2(int n) {
    int node = blockIdx.x * 8 + (threadIdx.x >> 5);
    if (node >= n) return;
    int lane = threadIdx.x & 31;
    int beg = g_rowptr[node], end = g_rowptr[node + 1];
    int cnt = end - beg;
    float4 acc = make_float4(0.f, 0.f, 0.f, 0.f);
    for (int base = beg; base < end; base += 32) {
        int m = min(end - base, 32);
        int sv = (lane < m) ? g_elist[base + lane] : 0;
        for (int j = 0; j < m; j++) {
            int s = __shfl_sync(0xffffffffu, sv, j);
            float4 v = g_h1[s * 32 + lane];
            acc.x += v.x; acc.y += v.y; acc.z += v.z; acc.w += v.w;
        }
    }
    float inv = 1.0f / fmaxf((float)cnt, 1.0f);
    acc.x *= inv; acc.y *= inv; acc.z *= inv; acc.w *= inv;
    g_agg1[node * 32 + lane] = acc;
}

// ---------------- conv2: tf32 MMA, 128-node tiles, K split in 2 phases -----
// Phase kh covers K range [kh*128, kh*128+128): kh=0 = agg part (Wl),
// kh=1 = h1 part (Wr). Accumulators carry across phases.
__global__ __launch_bounds__(256, 1) void k_conv2(const float* __restrict__ Wl,
        const float* __restrict__ bl, const float* __restrict__ Wr, int n) {
    extern __shared__ float sm[];
    float* Wc = sm;                    // [128][136] tf32, k-major (one K half)
    float* As = sm + 128 * 136;        // [128][132] tf32 (one K half)
    float* bs = As + 128 * 132;        // [128]
    unsigned* Wcu = (unsigned*)Wc;
    unsigned* Asu = (unsigned*)As;
    int tid = threadIdx.x;
    if (tid < 128) bs[tid] = bl[tid];
    int base = blockIdx.x * 128;
    int warp = tid >> 5, lane = tid & 31;
    int r = lane >> 2, tig = lane & 3;
    int mbase = warp * 16;
    float acc[16][4];
    #pragma unroll
    for (int a = 0; a < 16; a++) { acc[a][0] = acc[a][1] = acc[a][2] = acc[a][3] = 0.f; }
    #pragma unroll
    for (int kh = 0; kh < 2; kh++) {
        const float* Wsrc = kh ? Wr : Wl;
        for (int idx = tid; idx < 128 * 128; idx += 256) {
            int c = idx >> 7;
            int k = idx & 127;
            Wcu[k * 136 + c] = tf32u(Wsrc[c * 128 + k]);
        }
        for (int f = tid; f < 128 * 32; f += 256) {
            int nl = f >> 5, kq = f & 31;
            int node = base + nl;
            float4 v = make_float4(0.f, 0.f, 0.f, 0.f);
            if (node < n)
                v = kh ? g_h1[node * 32 + kq] : g_agg1[node * 32 + kq];
            uint4 u = make_uint4(tf32u(v.x), tf32u(v.y), tf32u(v.z), tf32u(v.w));
            *(uint4*)(Asu + nl * 132 + kq * 4) = u;
        }
        __syncthreads();
        for (int kb = 0; kb < 128; kb += 8) {
            unsigned a[4];
            a[0] = Asu[(mbase + r) * 132 + kb + tig];
            a[1] = Asu[(mbase + r + 8) * 132 + kb + tig];
            a[2] = Asu[(mbase + r) * 132 + kb + tig + 4];
            a[3] = Asu[(mbase + r + 8) * 132 + kb + tig + 4];
            #pragma unroll
            for (int nt = 0; nt < 16; nt++) {
                unsigned b[2];
                int ncol = nt * 8 + r;
                b[0] = Wcu[(kb + tig) * 136 + ncol];
                b[1] = Wcu[(kb + tig + 4) * 136 + ncol];
                mma_tf32(acc[nt], a, b);
            }
        }
        __syncthreads();
    }
    int node0 = base + mbase + r;
    int node1 = node0 + 8;
    #pragma unroll
    for (int nt = 0; nt < 16; nt++) {
        int col = nt * 8 + tig * 2;
        float b0 = bs[col], b1 = bs[col + 1];
        if (node0 < n) {
            float2 v = make_float2(tanhf(acc[nt][0] + b0), tanhf(acc[nt][1] + b1));
            *(float2*)((float*)g_h2 + node0 * 128 + col) = v;
        }
        if (node1 < n) {
            float2 v = make_float2(tanhf(acc[nt][2] + b0), tanhf(acc[nt][3] + b1));
            *(float2*)((float*)g_h2 + node1 * 128 + col) = v;
        }
    }
}

// ---------------- head: tf32 MMA, 128-node tiles; warp owns all 256 cols ---
// Each warp: 16 rows x 256 cols (32 n-subtiles). Epilogue: tanh + logits
// reduced within the quad only (no cross-warp combine needed).
__global__ __launch_bounds__(256, 1) void k_head(const float* __restrict__ W1,
        const float* __restrict__ b1, const float* __restrict__ W2,
        const float* __restrict__ b2, float* __restrict__ out, int n) {
    extern __shared__ float sm[];
    float* W1s = sm;                   // [128][264] tf32, k-major
    float* As  = W1s + 128 * 264;      // [128][132] tf32
    float* W2s = As + 128 * 132;       // [8][256] fp32
    float* b1s = W2s + 2048;           // [256]
    float* b2s = b1s + 256;            // [8]
    unsigned* W1u = (unsigned*)W1s;
    unsigned* Asu = (unsigned*)As;
    int tid = threadIdx.x;
    for (int idx = tid; idx < 256 * 128; idx += 256) {
        int c = idx >> 7;
        int k = idx & 127;
        W1u[k * 264 + c] = tf32u(W1[c * 128 + k]);
    }
    for (int idx = tid; idx < 2048; idx += 256) W2s[idx] = W2[idx];
    b1s[tid] = b1[tid];
    if (tid < 8) b2s[tid] = b2[tid];
    int base = blockIdx.x * 128;
    for (int f = tid; f < 128 * 32; f += 256) {
        int nl = f >> 5, kq = f & 31;
        int node = base + nl;
        float4 v = make_float4(0.f, 0.f, 0.f, 0.f);
        if (node < n) v = g_h2[node * 32 + kq];
        uint4 u = make_uint4(tf32u(v.x), tf32u(v.y), tf32u(v.z), tf32u(v.w));
        *(uint4*)(Asu + nl * 132 + kq * 4) = u;
    }
    __syncthreads();
    int warp = tid >> 5, lane = tid & 31;
    int r = lane >> 2, tig = lane & 3;
    int mbase = warp * 16;
    float acc[32][4];
    #pragma unroll
    for (int a = 0; a < 32; a++) { acc[a][0] = acc[a][1] = acc[a][2] = acc[a][3] = 0.f; }
    for (int kb = 0; kb < 128; kb += 8) {
        unsigned a[4];
        a[0] = Asu[(mbase + r) * 132 + kb + tig];
        a[1] = Asu[(mbase + r + 8) * 132 + kb + tig];
        a[2] = Asu[(mbase + r) * 132 + kb + tig + 4];
        a[3] = Asu[(mbase + r + 8) * 132 + kb + tig + 4];
        #pragma unroll
        for (int nt = 0; nt < 32; nt++) {
            unsigned b[2];
            int ncol = nt * 8 + r;
            b[0] = W1u[(kb + tig) * 264 + ncol];
            b[1] = W1u[(kb + tig + 4) * 264 + ncol];
            mma_tf32(acc[nt], a, b);
        }
    }
    // tanh + logits; this thread covers cols {nt*8 + tig*2, +1} over nt.
    float p0[8], p1[8];
    #pragma unroll
    for (int c = 0; c < 8; c++) { p0[c] = 0.f; p1[c] = 0.f; }
    #pragma unroll
    for (int nt = 0; nt < 32; nt++) {
        int col = nt * 8 + tig * 2;
        float t00 = tanhf(acc[nt][0] + b1s[col]);
        float t01 = tanhf(acc[nt][1] + b1s[col + 1]);
        float t10 = tanhf(acc[nt][2] + b1s[col]);
        float t11 = tanhf(acc[nt][3] + b1s[col + 1]);
        #pragma unroll
        for (int c = 0; c < 8; c++) {
            float w0 = W2s[c * 256 + col], w1 = W2s[c * 256 + col + 1];
            p0[c] += t00 * w0 + t01 * w1;
            p1[c] += t10 * w0 + t11 * w1;
        }
    }
    // reduce across the quad -> tig==0 holds full logits for both rows
    #pragma unroll
    for (int o = 1; o <= 2; o <<= 1) {
        #pragma unroll
        for (int c = 0; c < 8; c++) {
            p0[c] += __shfl_xor_sync(0xffffffffu, p0[c], o);
            p1[c] += __shfl_xor_sync(0xffffffffu, p1[c], o);
        }
    }
    if (tig == 0) {
        int node0 = base + mbase + r;
        int node1 = node0 + 8;
        if (node0 < n) {
            float l[8], m = -finf();
            #pragma unroll
            for (int c = 0; c < 8; c++) { l[c] = p0[c] + b2s[c]; m = fmaxf(m, l[c]); }
            float s = 0.f;
            #pragma unroll
            for (int c = 0; c < 8; c++) { l[c] = expf(l[c] - m); s += l[c]; }
            float inv = 1.0f / s;
            *(float4*)(out + node0 * 8)     = make_float4(l[0]*inv, l[1]*inv, l[2]*inv, l[3]*inv);
            *(float4*)(out + node0 * 8 + 4) = make_float4(l[4]*inv, l[5]*inv, l[6]*inv, l[7]*inv);
        }
        if (node1 < n) {
            float l[8], m = -finf();
            #pragma unroll
            for (int c = 0; c < 8; c++) { l[c] = p1[c] + b2s[c]; m = fmaxf(m, l[c]); }
            float s = 0.f;
            #pragma unroll
            for (int c = 0; c < 8; c++) { l[c] = expf(l[c] - m); s += l[c]; }
            float inv = 1.0f / s;
            *(float4*)(out + node1 * 8)     = make_float4(l[0]*inv, l[1]*inv, l[2]*inv, l[3]*inv);
            *(float4*)(out + node1 * 8 + 4) = make_float4(l[4]*inv, l[5]*inv, l[6]*inv, l[7]*inv);
        }
    }
}

// ---------------- launch ---------------------------------------------------
extern "C" void kernel_launch(void* const* d_in, const int* in_sizes, int n_in,
                              void* d_out, int out_size) {
    const float* x = 0; const int* ei = 0;
    const float *Wl1 = 0, *bl1 = 0, *Wr1 = 0, *Wl2 = 0, *bl2 = 0, *Wr2 = 0;
    const float *W1 = 0, *b1 = 0, *W2 = 0, *b2 = 0;
    int n = 100000, nE = 600000;
    for (int i = 0; i < n_in; i++) {
        int sz = in_sizes[i];
        const void* p = d_in[i];
        switch (sz) {
            case 300000:  x  = (const float*)p; n  = sz / 3; break;
            case 1200000: ei = (const int*)p; nE = sz / 2; break;
            case 384:     if (!Wl1) Wl1 = (const float*)p; else Wr1 = (const float*)p; break;
            case 128:     if (!bl1) bl1 = (const float*)p; else bl2 = (const float*)p; break;
            case 16384:   if (!Wl2) Wl2 = (const float*)p; else Wr2 = (const float*)p; break;
            case 32768:   W1 = (const float*)p; break;
            case 256:     b1 = (const float*)p; break;
            case 2048:    W2 = (const float*)p; break;
            case 8:       b2 = (const float*)p; break;
            default: break;
        }
    }
    float* out = (float*)d_out;
    if (n > NMAX) n = NMAX;
    if (nE > EMAX) nE = EMAX;

    const int SMEM_CONV2 = (128 * 136 + 128 * 132 + 128) * 4;                // 137.7 KB
    const int SMEM_HEAD  = (128 * 264 + 128 * 132 + 2048 + 256 + 8) * 4;     // 212.3 KB
    cudaFuncSetAttribute(k_conv2, cudaFuncAttributeMaxDynamicSharedMemorySize, SMEM_CONV2);
    cudaFuncSetAttribute(k_head,  cudaFuncAttributeMaxDynamicSharedMemorySize, SMEM_HEAD);

    int nb = (n + 255) / 256;
    int eb = (nE + 255) / 256;
    k_init<<<nb, 256>>>(ei, n);
    k_count<<<eb, 256>>>(ei, nE, n);
    k_scan1<<<nb, 256>>>(n);
    k_scan2<<<1, NBMAX>>>(nb, n);
    k_scan3<<<nb, 256>>>(n);
    k_fill<<<eb, 256>>>(ei, nE, n);
    k_stats1<<<nb, 256>>>(x, n);
    k_rot<<<nb, 256>>>(x, n);
    k_aggc1<<<nb, 256>>>(n);
    k_conv1<<<(n + 15) / 16, 256>>>(Wl1, bl1, Wr1, n);
    k_aggc2<<<(n + 7) / 8, 256>>>(n);
    k_conv2<<<(n + 127) / 128, 256, SMEM_CONV2>>>(Wl2, bl2, Wr2, n);
    k_head<<<(n + 127) / 128, 256, SMEM_HEAD>>>(W1, b1, W2, b2, out, n);
}